// round 2
// baseline (speedup 1.0000x reference)
#include <cuda_runtime.h>

#define NMAX 100000
#define EMAX 1000000
#define LMAX 200000
#define D 128

// Scratch (static device globals — allocation-free). float4 arrays guarantee
// 16B alignment for vector loads + red.global.v4 atomics.
__device__ float  g_deg[NMAX];
__device__ float  g_dinv[NMAX];
__device__ float4 g_h[(size_t)NMAX * 32];    // g = (x@W) * dinv[row]
__device__ float4 g_agg[(size_t)NMAX * 32];  // aggregation buffer (init = self term)
__device__ float4 g_x[(size_t)NMAX * 32];    // layer output
__device__ int    g_eidx[2 * EMAX];          // decoded src|dst
__device__ int    g_lidx[2 * LMAX];          // decoded label endpoints
__device__ int    g_is64;                    // index dtype flag

// ---------------------------------------------------------------------------
// dtype sniffing + index decode (robust to int32 or int64 storage)
// ---------------------------------------------------------------------------
__global__ void k_detect(const unsigned* __restrict__ w) {
    // int64 values < 2^31 have zero high words at odd 32-bit positions.
    int is64 = 1;
    for (int i = 0; i < 32; i++)
        if (w[2 * i + 1] != 0u) { is64 = 0; break; }
    g_is64 = is64;
}

__global__ void k_cvt(const void* __restrict__ raw, int* __restrict__ out,
                      int count, int n) {
    int i = blockIdx.x * blockDim.x + threadIdx.x;
    if (i >= count) return;
    long long v = g_is64 ? ((const long long*)raw)[i]
                         : (long long)((const int*)raw)[i];
    int x = (int)v;
    x = x < 0 ? 0 : (x >= n ? n - 1 : x);   // clamp: never crash
    out[i] = x;
}

// ---------------------------------------------------------------------------
// degree / normalization
// ---------------------------------------------------------------------------
__global__ void k_zero_deg(int n) {
    int i = blockIdx.x * blockDim.x + threadIdx.x;
    if (i < n) g_deg[i] = 0.0f;
}

__global__ void k_deg(int E) {
    int i = blockIdx.x * blockDim.x + threadIdx.x;
    if (i < E) atomicAdd(&g_deg[g_eidx[EMAX + i]], 1.0f);
}

__global__ void k_dinv(int n) {
    int i = blockIdx.x * blockDim.x + threadIdx.x;
    if (i < n) g_dinv[i] = rsqrtf(g_deg[i] + 1.0f);  // +1 self loop
}

// ---------------------------------------------------------------------------
// GEMM: g_h[row] = (X[row] @ W) * dinv[row];  g_agg[row] = g_h[row] (self loop)
// BM=64, BN=128 (full), BK=32; 256 threads; thread tile 8x4
// ---------------------------------------------------------------------------
__global__ void k_gemm_scale(const float* __restrict__ Xext,
                             const float* __restrict__ W,
                             int n, int use_internal) {
    const float* X = use_internal ? (const float*)g_x : Xext;

    __shared__ float As[64][32];   // [row][k]
    __shared__ float Ws[32][128];  // [k][col]

    int tid = threadIdx.x;
    int tx = tid & 31;   // col group: cols tx*4 .. tx*4+3
    int ty = tid >> 5;   // row group: rows ty*8 .. ty*8+7
    int rowBase = blockIdx.x * 64;

    float acc[8][4];
#pragma unroll
    for (int m = 0; m < 8; m++)
#pragma unroll
        for (int c = 0; c < 4; c++) acc[m][c] = 0.0f;

    for (int kk = 0; kk < 128; kk += 32) {
#pragma unroll
        for (int i = 0; i < 2; i++) {
            int idx = tid + i * 256;
            int r = idx >> 3;
            int q = idx & 7;
            int row = rowBase + r;
            float4 v = make_float4(0.f, 0.f, 0.f, 0.f);
            if (row < n)
                v = ((const float4*)(X + (size_t)row * 128 + kk))[q];
            ((float4*)&As[r][0])[q] = v;
        }
#pragma unroll
        for (int i = 0; i < 4; i++) {
            int idx = tid + i * 256;
            int k = idx >> 5;
            int q = idx & 31;
            ((float4*)&Ws[k][0])[q] =
                ((const float4*)(W + (size_t)(kk + k) * 128))[q];
        }
        __syncthreads();

#pragma unroll
        for (int k = 0; k < 32; k++) {
            float4 w4 = ((const float4*)&Ws[k][0])[tx];
            float a[8];
#pragma unroll
            for (int m = 0; m < 8; m++) a[m] = As[ty * 8 + m][k];
#pragma unroll
            for (int m = 0; m < 8; m++) {
                acc[m][0] = fmaf(a[m], w4.x, acc[m][0]);
                acc[m][1] = fmaf(a[m], w4.y, acc[m][1]);
                acc[m][2] = fmaf(a[m], w4.z, acc[m][2]);
                acc[m][3] = fmaf(a[m], w4.w, acc[m][3]);
            }
        }
        __syncthreads();
    }

#pragma unroll
    for (int m = 0; m < 8; m++) {
        int row = rowBase + ty * 8 + m;
        if (row < n) {
            float s = g_dinv[row];
            float4 v = make_float4(acc[m][0] * s, acc[m][1] * s,
                                   acc[m][2] * s, acc[m][3] * s);
            g_h[(size_t)row * 32 + tx] = v;
            g_agg[(size_t)row * 32 + tx] = v;  // self-loop term
        }
    }
}

// ---------------------------------------------------------------------------
// edge scatter: one warp per edge, lane = one float4 of the 128-dim row
// agg[dst] += g[src]   (norm folded out algebraically)
// ---------------------------------------------------------------------------
__device__ __forceinline__ void red_add_v4(float4* addr, float4 v) {
    asm volatile("red.global.add.v4.f32 [%0], {%1, %2, %3, %4};"
                 :: "l"(addr), "f"(v.x), "f"(v.y), "f"(v.z), "f"(v.w)
                 : "memory");
}

__global__ void k_scatter(int E) {
    int gw = (blockIdx.x * blockDim.x + threadIdx.x) >> 5;
    int lane = threadIdx.x & 31;
    if (gw >= E) return;
    int s = g_eidx[gw];
    int d = g_eidx[EMAX + gw];
    float4 v = g_h[(size_t)s * 32 + lane];
    red_add_v4(&g_agg[(size_t)d * 32 + lane], v);
}

// ---------------------------------------------------------------------------
// finalize: x = (relu?)(dinv[i] * agg[i] + b)  -> g_x
// ---------------------------------------------------------------------------
__global__ void k_finalize(const float* __restrict__ b, int n, int do_relu) {
    int i = blockIdx.x * blockDim.x + threadIdx.x;
    if (i >= n * 32) return;
    int node = i >> 5;
    int q = i & 31;
    float s = g_dinv[node];
    float4 a = g_agg[i];
    float4 bb = ((const float4*)b)[q];
    float4 r = make_float4(fmaf(s, a.x, bb.x), fmaf(s, a.y, bb.y),
                           fmaf(s, a.z, bb.z), fmaf(s, a.w, bb.w));
    if (do_relu) {
        r.x = fmaxf(r.x, 0.f); r.y = fmaxf(r.y, 0.f);
        r.z = fmaxf(r.z, 0.f); r.w = fmaxf(r.w, 0.f);
    }
    g_x[i] = r;
}

// ---------------------------------------------------------------------------
// edge scoring: one warp per label edge, dot over 128 dims
// ---------------------------------------------------------------------------
__global__ void k_score(float* __restrict__ out, int L) {
    int gw = (blockIdx.x * blockDim.x + threadIdx.x) >> 5;
    int lane = threadIdx.x & 31;
    if (gw >= L) return;
    int u = g_lidx[gw];
    int v = g_lidx[LMAX + gw];
    float4 xu = g_x[(size_t)u * 32 + lane];
    float4 xv = g_x[(size_t)v * 32 + lane];
    float p = xu.x * xv.x + xu.y * xv.y + xu.z * xv.z + xu.w * xv.w;
#pragma unroll
    for (int off = 16; off > 0; off >>= 1)
        p += __shfl_xor_sync(0xffffffffu, p, off);
    if (lane == 0) out[gw] = p;
}

// ---------------------------------------------------------------------------
static int* eidx_dev() {
    static int* p = nullptr;
    if (!p) cudaGetSymbolAddress((void**)&p, g_eidx);
    return p;
}
static int* lidx_dev() {
    static int* p = nullptr;
    if (!p) cudaGetSymbolAddress((void**)&p, g_lidx);
    return p;
}

extern "C" void kernel_launch(void* const* d_in, const int* in_sizes, int n_in,
                              void* d_out, int out_size) {
    const float* X   = (const float*)d_in[0];
    const void* eidx = d_in[1];
    const void* lidx = d_in[2];
    const float* W1  = (const float*)d_in[3];
    const float* b1  = (const float*)d_in[4];
    const float* W2  = (const float*)d_in[5];
    const float* b2  = (const float*)d_in[6];

    int N = in_sizes[0] / 128;
    int E = in_sizes[1] / 2;
    int L = in_sizes[2] / 2;

    // decode indices (dtype-robust, clamped)
    k_detect<<<1, 1>>>((const unsigned*)eidx);
    k_cvt<<<(2 * E + 255) / 256, 256>>>(eidx, eidx_dev(), 2 * E, N);
    k_cvt<<<(2 * L + 255) / 256, 256>>>(lidx, lidx_dev(), 2 * L, N);

    // degrees -> dinv
    k_zero_deg<<<(N + 255) / 256, 256>>>(N);
    k_deg<<<(E + 255) / 256, 256>>>(E);
    k_dinv<<<(N + 255) / 256, 256>>>(N);

    int gemmBlocks  = (N + 63) / 64;
    int scatBlocks  = (E + 7) / 8;
    int finBlocks   = (N * 32 + 255) / 256;
    int scoreBlocks = (L + 7) / 8;

    // layer 1
    k_gemm_scale<<<gemmBlocks, 256>>>(X, W1, N, 0);
    k_scatter<<<scatBlocks, 256>>>(E);
    k_finalize<<<finBlocks, 256>>>(b1, N, 1);

    // layer 2
    k_gemm_scale<<<gemmBlocks, 256>>>(X, W2, N, 1);
    k_scatter<<<scatBlocks, 256>>>(E);
    k_finalize<<<finBlocks, 256>>>(b2, N, 0);

    // link prediction scores
    k_score<<<scoreBlocks, 256>>>((float*)d_out, L);
}

// round 3
// speedup vs baseline: 1.5876x; 1.5876x over previous
#include <cuda_runtime.h>

#define NMAX 100000
#define EMAX 1000000
#define LMAX 200000

// ---------------------------------------------------------------------------
// Static device scratch (allocation-free)
// ---------------------------------------------------------------------------
__device__ int    g_deg[NMAX];
__device__ float  g_dinv[NMAX];
__device__ int    g_off[NMAX];               // CSR row offsets (exclusive scan of deg)
__device__ int    g_cur[NMAX];               // fill cursors
__device__ int    g_bsum[256];               // scan block sums
__device__ int    g_csr[EMAX];               // CSR: src node per slot
__device__ float4 g_h[(size_t)NMAX * 32];    // h = (x@W)*dinv[row]
__device__ float4 g_x[(size_t)NMAX * 32];    // layer output
__device__ int    g_eidx[2 * EMAX];          // decoded src|dst
__device__ int    g_lidx[2 * LMAX];          // decoded label endpoints
__device__ int    g_is64;

// ---------------------------------------------------------------------------
// f32x2 packed-FMA helpers (sm_103a dual-rate fp32 path)
// ---------------------------------------------------------------------------
__device__ __forceinline__ unsigned long long fma2(unsigned long long a,
                                                   unsigned long long b,
                                                   unsigned long long c) {
    unsigned long long d;
    asm("fma.rn.f32x2 %0, %1, %2, %3;" : "=l"(d) : "l"(a), "l"(b), "l"(c));
    return d;
}
__device__ __forceinline__ unsigned long long pack2(float lo, float hi) {
    unsigned long long o;
    asm("mov.b64 %0, {%1, %2};" : "=l"(o) : "f"(lo), "f"(hi));
    return o;
}
__device__ __forceinline__ void unpack2(unsigned long long v, float& lo, float& hi) {
    asm("mov.b64 {%0, %1}, %2;" : "=f"(lo), "=f"(hi) : "l"(v));
}

// ---------------------------------------------------------------------------
// dtype sniffing + decode (robust to int32 or int64 index storage)
// ---------------------------------------------------------------------------
__global__ void k_detect(const unsigned* __restrict__ w) {
    int is64 = 1;
    for (int i = 0; i < 32; i++)
        if (w[2 * i + 1] != 0u) { is64 = 0; break; }
    g_is64 = is64;
}

__global__ void k_zero2(int n) {  // zero deg + cur
    int i = blockIdx.x * blockDim.x + threadIdx.x;
    if (i < n) { g_deg[i] = 0; g_cur[i] = 0; }
}

__global__ void k_cvt_lbl(const void* __restrict__ raw, int count, int n) {
    int i = blockIdx.x * blockDim.x + threadIdx.x;
    if (i >= count) return;
    long long v = g_is64 ? ((const long long*)raw)[i]
                         : (long long)((const int*)raw)[i];
    int x = (int)v;
    x = x < 0 ? 0 : (x >= n ? n - 1 : x);
    g_lidx[i] = x;
}

// decode edges + histogram dst degrees in the same pass
__global__ void k_cvt_edges(const void* __restrict__ raw, int twoE, int E, int n) {
    int i = blockIdx.x * blockDim.x + threadIdx.x;
    if (i >= twoE) return;
    long long v = g_is64 ? ((const long long*)raw)[i]
                         : (long long)((const int*)raw)[i];
    int x = (int)v;
    x = x < 0 ? 0 : (x >= n ? n - 1 : x);
    g_eidx[i] = x;
    if (i >= E) atomicAdd(&g_deg[x], 1);   // dst half
}

// ---------------------------------------------------------------------------
// 3-kernel exclusive scan of deg -> off  (512 elems/block; n<=131072)
// scan1 also computes dinv = rsqrt(deg+1)
// ---------------------------------------------------------------------------
__global__ void k_scan1(int n) {
    __shared__ int s[512];
    int t = threadIdx.x;
    int i = blockIdx.x * 512 + t;
    int v = (i < n) ? g_deg[i] : 0;
    if (i < n) g_dinv[i] = rsqrtf((float)v + 1.0f);
    s[t] = v;
    __syncthreads();
    for (int off = 1; off < 512; off <<= 1) {
        int add = (t >= off) ? s[t - off] : 0;
        __syncthreads();
        s[t] += add;
        __syncthreads();
    }
    if (i < n) g_off[i] = s[t] - v;          // exclusive
    if (t == 511) g_bsum[blockIdx.x] = s[511];
}

__global__ void k_scan2(int nb) {
    __shared__ int s[256];
    int t = threadIdx.x;
    int v = (t < nb) ? g_bsum[t] : 0;
    s[t] = v;
    __syncthreads();
    for (int off = 1; off < 256; off <<= 1) {
        int add = (t >= off) ? s[t - off] : 0;
        __syncthreads();
        s[t] += add;
        __syncthreads();
    }
    if (t < nb) g_bsum[t] = s[t] - v;        // exclusive
}

__global__ void k_scan3(int n) {
    int i = blockIdx.x * blockDim.x + threadIdx.x;
    if (i < n) g_off[i] += g_bsum[i >> 9];
}

__global__ void k_fill(int E) {
    int i = blockIdx.x * blockDim.x + threadIdx.x;
    if (i >= E) return;
    int s = g_eidx[i];
    int d = g_eidx[E + i];
    int pos = g_off[d] + atomicAdd(&g_cur[d], 1);
    g_csr[pos] = s;
}

// ---------------------------------------------------------------------------
// GEMM: g_h[row] = (X[row] @ W) * dinv[row]
// BM=128, BN=128(full), BK=32; 256 threads (16x16); 8x8/thread via f32x2
// ---------------------------------------------------------------------------
__global__ void __launch_bounds__(256)
k_gemm(const float* __restrict__ Xext, const float* __restrict__ W,
       int n, int use_internal) {
    const float* X = use_internal ? (const float*)g_x : Xext;

    __shared__ float As[32][132];   // [k][row], padded (16B-aligned rows)
    __shared__ float Ws[32][132];   // [k][col], padded

    int tid = threadIdx.x;
    int tx = tid & 15;              // col group: cols tx*8 .. tx*8+7
    int ty = tid >> 4;              // row group: rows ty*8 .. ty*8+7
    int rowBase = blockIdx.x * 128;

    unsigned long long acc[8][4];   // [m][col-pair] 2 floats each
#pragma unroll
    for (int m = 0; m < 8; m++)
#pragma unroll
        for (int c = 0; c < 4; c++) acc[m][c] = 0ull;

    for (int kk = 0; kk < 128; kk += 32) {
        // load A tile (transposed into smem): 128 rows x 32 k
#pragma unroll
        for (int i = 0; i < 4; i++) {
            int fi = tid + i * 256;       // 0..1023
            int r = fi >> 3;              // row in tile
            int q = fi & 7;               // float4 group along k (q*4)
            int row = rowBase + r;
            float4 v = make_float4(0.f, 0.f, 0.f, 0.f);
            if (row < n)
                v = *(const float4*)(X + (size_t)row * 128 + kk + q * 4);
            As[q * 4 + 0][r] = v.x;
            As[q * 4 + 1][r] = v.y;
            As[q * 4 + 2][r] = v.z;
            As[q * 4 + 3][r] = v.w;
        }
        // load W tile: 32 k x 128 cols
#pragma unroll
        for (int i = 0; i < 4; i++) {
            int fi = tid + i * 256;       // 0..1023
            int k = fi >> 5;
            int q = fi & 31;
            float4 v = *(const float4*)(W + (size_t)(kk + k) * 128 + q * 4);
            *(float4*)&Ws[k][q * 4] = v;
        }
        __syncthreads();

#pragma unroll
        for (int k = 0; k < 32; k++) {
            // a: 8 rows as 2 float4, duplicated into f32x2 pairs
            float4 a0 = *(const float4*)&As[k][ty * 8];
            float4 a1 = *(const float4*)&As[k][ty * 8 + 4];
            unsigned long long ap[8];
            ap[0] = pack2(a0.x, a0.x); ap[1] = pack2(a0.y, a0.y);
            ap[2] = pack2(a0.z, a0.z); ap[3] = pack2(a0.w, a0.w);
            ap[4] = pack2(a1.x, a1.x); ap[5] = pack2(a1.y, a1.y);
            ap[6] = pack2(a1.z, a1.z); ap[7] = pack2(a1.w, a1.w);
            // w: 8 cols = 4 packed pairs (bit-reinterpret of smem float pairs)
            const unsigned long long* wp =
                (const unsigned long long*)&Ws[k][tx * 8];
            unsigned long long w0 = wp[0], w1 = wp[1], w2 = wp[2], w3 = wp[3];
#pragma unroll
            for (int m = 0; m < 8; m++) {
                acc[m][0] = fma2(ap[m], w0, acc[m][0]);
                acc[m][1] = fma2(ap[m], w1, acc[m][1]);
                acc[m][2] = fma2(ap[m], w2, acc[m][2]);
                acc[m][3] = fma2(ap[m], w3, acc[m][3]);
            }
        }
        __syncthreads();
    }

#pragma unroll
    for (int m = 0; m < 8; m++) {
        int row = rowBase + ty * 8 + m;
        if (row < n) {
            float s = g_dinv[row];
            float4 v0, v1;
            unpack2(acc[m][0], v0.x, v0.y);
            unpack2(acc[m][1], v0.z, v0.w);
            unpack2(acc[m][2], v1.x, v1.y);
            unpack2(acc[m][3], v1.z, v1.w);
            v0.x *= s; v0.y *= s; v0.z *= s; v0.w *= s;
            v1.x *= s; v1.y *= s; v1.z *= s; v1.w *= s;
            g_h[(size_t)row * 32 + tx * 2 + 0] = v0;
            g_h[(size_t)row * 32 + tx * 2 + 1] = v1;
        }
    }
}

// ---------------------------------------------------------------------------
// CSR pull aggregation + fused finalize:
// x[d] = act( dinv[d] * (h[d] + sum_{s in nbr(d)} h[s]) + b )
// one warp per node, lane = float4 slice
// ---------------------------------------------------------------------------
__global__ void k_agg(const float* __restrict__ bias, int n, int do_relu) {
    int gw = (blockIdx.x * blockDim.x + threadIdx.x) >> 5;
    int lane = threadIdx.x & 31;
    if (gw >= n) return;
    int d = gw;

    float4 acc = g_h[(size_t)d * 32 + lane];       // self-loop term
    int o = g_off[d];
    int c = g_deg[d];

    int j = 0;
    for (; j + 4 <= c; j += 4) {
        int s0 = g_csr[o + j + 0];
        int s1 = g_csr[o + j + 1];
        int s2 = g_csr[o + j + 2];
        int s3 = g_csr[o + j + 3];
        float4 v0 = g_h[(size_t)s0 * 32 + lane];
        float4 v1 = g_h[(size_t)s1 * 32 + lane];
        float4 v2 = g_h[(size_t)s2 * 32 + lane];
        float4 v3 = g_h[(size_t)s3 * 32 + lane];
        acc.x += v0.x + v1.x + v2.x + v3.x;
        acc.y += v0.y + v1.y + v2.y + v3.y;
        acc.z += v0.z + v1.z + v2.z + v3.z;
        acc.w += v0.w + v1.w + v2.w + v3.w;
    }
    for (; j < c; j++) {
        int s = g_csr[o + j];
        float4 v = g_h[(size_t)s * 32 + lane];
        acc.x += v.x; acc.y += v.y; acc.z += v.z; acc.w += v.w;
    }

    float sc = g_dinv[d];
    float4 bv = ((const float4*)bias)[lane];
    float4 r = make_float4(fmaf(sc, acc.x, bv.x), fmaf(sc, acc.y, bv.y),
                           fmaf(sc, acc.z, bv.z), fmaf(sc, acc.w, bv.w));
    if (do_relu) {
        r.x = fmaxf(r.x, 0.f); r.y = fmaxf(r.y, 0.f);
        r.z = fmaxf(r.z, 0.f); r.w = fmaxf(r.w, 0.f);
    }
    g_x[(size_t)d * 32 + lane] = r;
}

// ---------------------------------------------------------------------------
// edge scoring: one warp per label edge, dot over 128 dims
// ---------------------------------------------------------------------------
__global__ void k_score(float* __restrict__ out, int L) {
    int gw = (blockIdx.x * blockDim.x + threadIdx.x) >> 5;
    int lane = threadIdx.x & 31;
    if (gw >= L) return;
    int u = g_lidx[gw];
    int v = g_lidx[LMAX ? (L + gw) : 0];   // label layout: [u(0..L), v(L..2L)]
    float4 xu = g_x[(size_t)u * 32 + lane];
    float4 xv = g_x[(size_t)v * 32 + lane];
    float p = xu.x * xv.x + xu.y * xv.y + xu.z * xv.z + xu.w * xv.w;
#pragma unroll
    for (int off = 16; off > 0; off >>= 1)
        p += __shfl_xor_sync(0xffffffffu, p, off);
    if (lane == 0) out[gw] = p;
}

// ---------------------------------------------------------------------------
extern "C" void kernel_launch(void* const* d_in, const int* in_sizes, int n_in,
                              void* d_out, int out_size) {
    const float* X   = (const float*)d_in[0];
    const void* eidx = d_in[1];
    const void* lidx = d_in[2];
    const float* W1  = (const float*)d_in[3];
    const float* b1  = (const float*)d_in[4];
    const float* W2  = (const float*)d_in[5];
    const float* b2  = (const float*)d_in[6];

    int N = in_sizes[0] / 128;
    int E = in_sizes[1] / 2;
    int L = in_sizes[2] / 2;

    int nb1 = (N + 511) / 512;               // scan blocks (<=256 for N<=131072)

    // Launch order places k_gemm (layer 1) at position 6 so ncu's
    // "-s 5 -c 1" capture profiles the GEMM.
    k_detect<<<1, 1>>>((const unsigned*)eidx);                       // 1
    k_zero2<<<(N + 255) / 256, 256>>>(N);                            // 2
    k_cvt_lbl<<<(2 * L + 255) / 256, 256>>>(lidx, 2 * L, N);         // 3
    k_cvt_edges<<<(2 * E + 255) / 256, 256>>>(eidx, 2 * E, E, N);    // 4
    k_scan1<<<nb1, 512>>>(N);                                        // 5
    k_gemm<<<(N + 127) / 128, 256>>>(X, W1, N, 0);                   // 6 <- ncu
    k_scan2<<<1, 256>>>(nb1);                                        // 7
    k_scan3<<<(N + 255) / 256, 256>>>(N);                            // 8
    k_fill<<<(E + 255) / 256, 256>>>(E);                             // 9
    k_agg<<<(N + 7) / 8, 256>>>(b1, N, 1);                           // 10
    k_gemm<<<(N + 127) / 128, 256>>>(X, W2, N, 1);                   // 11
    k_agg<<<(N + 7) / 8, 256>>>(b2, N, 0);                           // 12
    k_score<<<(L + 7) / 8, 256>>>((float*)d_out, L);                 // 13
}